// round 1
// baseline (speedup 1.0000x reference)
#include <cuda_runtime.h>
#include <math.h>

#define N_NODES 20000
#define N_EDGES 640000
#define FIN_DIM 256
#define HDIM 512
#define TOPK 1000
#define SORT_N 32768

// ---------------- scratch (static device memory; no allocations) ----------------
__device__ float g_agg[(size_t)N_NODES * HDIM];
__device__ float g_tmp[(size_t)N_NODES * HDIM];
__device__ float g_act[(size_t)N_NODES * HDIM];
__device__ float g_o1[N_NODES * 2];
__device__ float g_o2[N_NODES * 2];
__device__ float g_sort[SORT_N];
__device__ int   g_cnt[N_NODES];
__device__ int   g_rowptr[N_NODES + 1];
__device__ int   g_cursor[N_NODES];
__device__ int   g_esrc[N_EDGES];

// ---------------- CSR build ----------------
__global__ void k_zero_cnt() {
    int i = blockIdx.x * blockDim.x + threadIdx.x;
    if (i < N_NODES) g_cnt[i] = 0;
}

__global__ void k_hist(const int* __restrict__ dst) {
    int e = blockIdx.x * blockDim.x + threadIdx.x;
    if (e < N_EDGES) atomicAdd(&g_cnt[dst[e]], 1);
}

__global__ void k_scan() {
    __shared__ int s[1024];
    __shared__ int carry;
    int t = threadIdx.x;
    if (t == 0) carry = 0;
    __syncthreads();
    for (int base = 0; base < N_NODES; base += 1024) {
        int v = (base + t < N_NODES) ? g_cnt[base + t] : 0;
        s[t] = v;
        __syncthreads();
        for (int off = 1; off < 1024; off <<= 1) {
            int a = (t >= off) ? s[t - off] : 0;
            __syncthreads();
            s[t] += a;
            __syncthreads();
        }
        int exc = s[t] - v + carry;
        if (base + t < N_NODES) { g_rowptr[base + t] = exc; g_cursor[base + t] = exc; }
        __syncthreads();
        if (t == 0) carry = carry + s[1023];
        __syncthreads();
    }
    if (t == 0) g_rowptr[N_NODES] = carry;
}

__global__ void k_fill(const int* __restrict__ src, const int* __restrict__ dst) {
    int e = blockIdx.x * blockDim.x + threadIdx.x;
    if (e < N_EDGES) {
        int d = dst[e];
        int pos = atomicAdd(&g_cursor[d], 1);
        g_esrc[pos] = src[e];
    }
}

// ---------------- aggregation: out[i] = x[i] + sum_{j->i} x[j] ----------------
template <int F>
__global__ void k_agg(const float* __restrict__ x, float* __restrict__ out) {
    const int FV = F / 4;
    int node = blockIdx.x;
    int t = threadIdx.x;  // FV threads
    __shared__ int ssrc[256];
    const float4* x4 = (const float4*)x;
    float4 acc = x4[(size_t)node * FV + t];
    int beg = g_rowptr[node], end = g_rowptr[node + 1];
    for (int c = beg; c < end; c += 256) {
        int m = min(256, end - c);
        for (int i = t; i < m; i += FV) ssrc[i] = g_esrc[c + i];
        __syncthreads();
        for (int i = 0; i < m; i++) {
            float4 v = x4[(size_t)ssrc[i] * FV + t];
            acc.x += v.x; acc.y += v.y; acc.z += v.z; acc.w += v.w;
        }
        __syncthreads();
    }
    ((float4*)out)[(size_t)node * FV + t] = acc;
}

// ---------------- GEMM: C[M,512] = relu?(A[M,K] @ W[K,512] + b) ----------------
#define BM 128
#define BN 64
#define BK 16
#define TM 8
#define TN 4

__global__ void __launch_bounds__(256, 4)
k_gemm(const float* __restrict__ A, const float* __restrict__ W,
       const float* __restrict__ bias, float* __restrict__ C,
       int M, int K, int do_relu) {
    const int N = HDIM;
    __shared__ float As[BK][BM];
    __shared__ float Bs[BK][BN];
    int t = threadIdx.x;
    int tx = t & 15, ty = t >> 4;
    int rowBase = blockIdx.y * BM;
    int colBase = blockIdx.x * BN;
    float acc[TM][TN];
#pragma unroll
    for (int i = 0; i < TM; i++)
#pragma unroll
        for (int j = 0; j < TN; j++) acc[i][j] = 0.f;

    for (int k0 = 0; k0 < K; k0 += BK) {
        // load A tile (128x16) as 2 float4 per thread
#pragma unroll
        for (int r = 0; r < 2; r++) {
            int id = t + r * 256;
            int ar = id >> 2, aq = id & 3;
            int grow = rowBase + ar;
            float4 v = make_float4(0.f, 0.f, 0.f, 0.f);
            if (grow < M) v = *(const float4*)&A[(size_t)grow * K + k0 + aq * 4];
            As[aq * 4 + 0][ar] = v.x;
            As[aq * 4 + 1][ar] = v.y;
            As[aq * 4 + 2][ar] = v.z;
            As[aq * 4 + 3][ar] = v.w;
        }
        // load B tile (16x64): one float4 per thread
        {
            float4 v = *(const float4*)&W[(size_t)(k0 + ty) * N + colBase + tx * 4];
            *(float4*)&Bs[ty][tx * 4] = v;
        }
        __syncthreads();
#pragma unroll
        for (int kk = 0; kk < BK; kk++) {
            float a[TM], b[TN];
            float4 a0 = *(const float4*)&As[kk][ty * 8];
            float4 a1 = *(const float4*)&As[kk][ty * 8 + 4];
            a[0] = a0.x; a[1] = a0.y; a[2] = a0.z; a[3] = a0.w;
            a[4] = a1.x; a[5] = a1.y; a[6] = a1.z; a[7] = a1.w;
            float4 bv = *(const float4*)&Bs[kk][tx * 4];
            b[0] = bv.x; b[1] = bv.y; b[2] = bv.z; b[3] = bv.w;
#pragma unroll
            for (int i = 0; i < TM; i++)
#pragma unroll
                for (int j = 0; j < TN; j++) acc[i][j] += a[i] * b[j];
        }
        __syncthreads();
    }
    float4 bv = *(const float4*)&bias[colBase + tx * 4];
#pragma unroll
    for (int i = 0; i < TM; i++) {
        int grow = rowBase + ty * 8 + i;
        if (grow < M) {
            float4 o;
            o.x = acc[i][0] + bv.x;
            o.y = acc[i][1] + bv.y;
            o.z = acc[i][2] + bv.z;
            o.w = acc[i][3] + bv.w;
            if (do_relu) {
                o.x = fmaxf(o.x, 0.f); o.y = fmaxf(o.y, 0.f);
                o.z = fmaxf(o.z, 0.f); o.w = fmaxf(o.w, 0.f);
            }
            *(float4*)&C[(size_t)grow * N + colBase + tx * 4] = o;
        }
    }
}

// ---------------- final linear [N,512] @ [512,2] ----------------
__global__ void k_lin(const float* __restrict__ act, const float* __restrict__ w,
                      const float* __restrict__ b, float* __restrict__ o) {
    int warp = (blockIdx.x * blockDim.x + threadIdx.x) >> 5;
    int lane = threadIdx.x & 31;
    if (warp >= N_NODES) return;
    float a0 = 0.f, a1 = 0.f;
    for (int k = lane; k < HDIM; k += 32) {
        float v = act[(size_t)warp * HDIM + k];
        a0 += v * w[k * 2];
        a1 += v * w[k * 2 + 1];
    }
#pragma unroll
    for (int off = 16; off; off >>= 1) {
        a0 += __shfl_down_sync(0xffffffffu, a0, off);
        a1 += __shfl_down_sync(0xffffffffu, a1, off);
    }
    if (lane == 0) {
        o[warp * 2]     = a0 + b[0];
        o[warp * 2 + 1] = a1 + b[1];
    }
}

// ---------------- pairwise distance + pad ----------------
__global__ void k_dist() {
    int i = blockIdx.x * blockDim.x + threadIdx.x;
    if (i >= SORT_N) return;
    if (i < N_NODES) {
        float dx = g_o1[i * 2]     - g_o2[i * 2]     + 1e-6f;
        float dy = g_o1[i * 2 + 1] - g_o2[i * 2 + 1] + 1e-6f;
        g_sort[i] = sqrtf(dx * dx + dy * dy);
    } else {
        g_sort[i] = -INFINITY;
    }
}

// ---------------- single-block bitonic sort (descending) ----------------
__global__ void k_sort() {
    extern __shared__ float s[];
    int t = threadIdx.x;
    for (int i = t; i < SORT_N; i += 1024) s[i] = g_sort[i];
    __syncthreads();
    for (int k = 2; k <= SORT_N; k <<= 1) {
        for (int j = k >> 1; j > 0; j >>= 1) {
            for (int i = t; i < SORT_N; i += 1024) {
                int ixj = i ^ j;
                if (ixj > i) {
                    bool dsc = (i & k) == 0;  // descending overall
                    float a = s[i], c = s[ixj];
                    bool sw = dsc ? (a < c) : (a > c);
                    if (sw) { s[i] = c; s[ixj] = a; }
                }
            }
            __syncthreads();
        }
    }
    for (int i = t; i < TOPK; i += 1024) g_sort[i] = s[i];
}

// ---------------- head MLP (single block, 512 threads) ----------------
__global__ void k_mlp(const float* __restrict__ fc1w, const float* __restrict__ fc1b,
                      const float* __restrict__ ln1g, const float* __restrict__ ln1b,
                      const float* __restrict__ fc2w, const float* __restrict__ fc2b,
                      const float* __restrict__ ln2g, const float* __restrict__ ln2b,
                      const float* __restrict__ fc3w, const float* __restrict__ fc3b,
                      float* __restrict__ out) {
    __shared__ float vals[TOPK];
    __shared__ float h1[128];
    __shared__ float part[4][128];
    __shared__ float h2[512];
    __shared__ float red[512];
    int t = threadIdx.x;  // 512 threads
    for (int i = t; i < TOPK; i += 512) vals[i] = g_sort[i];
    __syncthreads();
    // fc1: [1000] @ [1000,128]
    {
        int j = t & 127, c = t >> 7;
        float acc = 0.f;
        for (int i = c * 250; i < (c + 1) * 250; i++) acc += vals[i] * fc1w[i * 128 + j];
        part[c][j] = acc;
    }
    __syncthreads();
    if (t < 128) h1[t] = part[0][t] + part[1][t] + part[2][t] + part[3][t] + fc1b[t];
    __syncthreads();
    // LN(128) + relu
    red[t] = (t < 128) ? h1[t] : 0.f;
    __syncthreads();
    for (int off = 256; off; off >>= 1) { if (t < off) red[t] += red[t + off]; __syncthreads(); }
    float mean1 = red[0] / 128.f;
    __syncthreads();
    red[t] = (t < 128) ? (h1[t] - mean1) * (h1[t] - mean1) : 0.f;
    __syncthreads();
    for (int off = 256; off; off >>= 1) { if (t < off) red[t] += red[t + off]; __syncthreads(); }
    float var1 = red[0] / 128.f;
    __syncthreads();
    if (t < 128) {
        float v = (h1[t] - mean1) * rsqrtf(var1 + 1e-5f) * ln1g[t] + ln1b[t];
        h1[t] = fmaxf(v, 0.f);
    }
    __syncthreads();
    // fc2: [128] @ [128,512]
    {
        float acc = fc2b[t];
        for (int i = 0; i < 128; i++) acc += h1[i] * fc2w[i * 512 + t];
        h2[t] = acc;
    }
    __syncthreads();
    // LN(512) + relu
    red[t] = h2[t];
    __syncthreads();
    for (int off = 256; off; off >>= 1) { if (t < off) red[t] += red[t + off]; __syncthreads(); }
    float mean2 = red[0] / 512.f;
    __syncthreads();
    red[t] = (h2[t] - mean2) * (h2[t] - mean2);
    __syncthreads();
    for (int off = 256; off; off >>= 1) { if (t < off) red[t] += red[t + off]; __syncthreads(); }
    float var2 = red[0] / 512.f;
    __syncthreads();
    float hr = fmaxf((h2[t] - mean2) * rsqrtf(var2 + 1e-5f) * ln2g[t] + ln2b[t], 0.f);
    red[t] = hr * fc3w[t];
    __syncthreads();
    for (int off = 256; off; off >>= 1) { if (t < off) red[t] += red[t + off]; __syncthreads(); }
    if (t == 0) out[0] = 1.f / (1.f + expf(-(red[0] + fc3b[0])));
}

// ---------------- launch ----------------
extern "C" void kernel_launch(void* const* d_in, const int* in_sizes, int n_in,
                              void* d_out, int out_size) {
    const float* x1   = (const float*)d_in[0];
    const int*   ei1  = (const int*)d_in[1];
    const float* x2   = (const float*)d_in[2];
    const int*   ei2  = (const int*)d_in[3];
    const float* w11  = (const float*)d_in[4];
    const float* b11  = (const float*)d_in[5];
    const float* w12  = (const float*)d_in[6];
    const float* b12  = (const float*)d_in[7];
    const float* w21  = (const float*)d_in[8];
    const float* b21  = (const float*)d_in[9];
    const float* w22  = (const float*)d_in[10];
    const float* b22  = (const float*)d_in[11];
    const float* w31  = (const float*)d_in[12];
    const float* b31  = (const float*)d_in[13];
    const float* w32  = (const float*)d_in[14];
    const float* b32  = (const float*)d_in[15];
    const float* linw = (const float*)d_in[16];
    const float* linb = (const float*)d_in[17];
    const float* fc1w = (const float*)d_in[18];
    const float* fc1b = (const float*)d_in[19];
    const float* ln1g = (const float*)d_in[20];
    const float* ln1b = (const float*)d_in[21];
    const float* fc2w = (const float*)d_in[22];
    const float* fc2b = (const float*)d_in[23];
    const float* ln2g = (const float*)d_in[24];
    const float* ln2b = (const float*)d_in[25];
    const float* fc3w = (const float*)d_in[26];
    const float* fc3b = (const float*)d_in[27];
    float* out = (float*)d_out;

    float *p_agg, *p_tmp, *p_act, *p_o1, *p_o2;
    cudaGetSymbolAddress((void**)&p_agg, g_agg);
    cudaGetSymbolAddress((void**)&p_tmp, g_tmp);
    cudaGetSymbolAddress((void**)&p_act, g_act);
    cudaGetSymbolAddress((void**)&p_o1, g_o1);
    cudaGetSymbolAddress((void**)&p_o2, g_o2);

    cudaFuncSetAttribute(k_sort, cudaFuncAttributeMaxDynamicSharedMemorySize, SORT_N * 4);

    dim3 gemm_grid(HDIM / BN, (N_NODES + BM - 1) / BM);
    const int EB = (N_EDGES + 255) / 256;
    const int NB = (N_NODES + 255) / 256;

    for (int g = 0; g < 2; g++) {
        const float* x   = g ? x2 : x1;
        const int*   src = g ? ei2 : ei1;
        const int*   dst = src + N_EDGES;
        float*       o   = g ? p_o2 : p_o1;

        // build CSR (by dst) for this graph
        k_zero_cnt<<<NB, 256>>>();
        k_hist<<<EB, 256>>>(dst);
        k_scan<<<1, 1024>>>();
        k_fill<<<EB, 256>>>(src, dst);

        // layer 1 (FIN=256 -> H)
        k_agg<FIN_DIM><<<N_NODES, FIN_DIM / 4>>>(x, p_agg);
        k_gemm<<<gemm_grid, 256>>>(p_agg, w11, b11, p_tmp, N_NODES, FIN_DIM, 1);
        k_gemm<<<gemm_grid, 256>>>(p_tmp, w12, b12, p_act, N_NODES, HDIM, 1);
        // layer 2
        k_agg<HDIM><<<N_NODES, HDIM / 4>>>(p_act, p_agg);
        k_gemm<<<gemm_grid, 256>>>(p_agg, w21, b21, p_tmp, N_NODES, HDIM, 1);
        k_gemm<<<gemm_grid, 256>>>(p_tmp, w22, b22, p_act, N_NODES, HDIM, 1);
        // layer 3
        k_agg<HDIM><<<N_NODES, HDIM / 4>>>(p_act, p_agg);
        k_gemm<<<gemm_grid, 256>>>(p_agg, w31, b31, p_tmp, N_NODES, HDIM, 1);
        k_gemm<<<gemm_grid, 256>>>(p_tmp, w32, b32, p_act, N_NODES, HDIM, 1);
        // lin head -> [N,2]
        k_lin<<<(N_NODES * 32 + 255) / 256, 256>>>(p_act, linw, linb, o);
    }

    k_dist<<<SORT_N / 256, 256>>>();
    k_sort<<<1, 1024, SORT_N * 4>>>();
    k_mlp<<<1, 512>>>(fc1w, fc1b, ln1g, ln1b, fc2w, fc2b, ln2g, ln2b, fc3w, fc3b, out);
}

// round 3
// speedup vs baseline: 1.2018x; 1.2018x over previous
#include <cuda_runtime.h>
#include <math.h>
#include <stdint.h>

#define N_NODES 20000
#define MPAD    20096
#define MT      157
#define N_EDGES 640000
#define FIN_DIM 256
#define HDIM 512
#define TOPK 1000
#define SORT_N 32768

// ---------------- scratch (static device memory; no allocations) ----------------
__device__ float g_agg[(size_t)MPAD * HDIM];
__device__ float g_tmp[(size_t)MPAD * HDIM];
__device__ float g_act[(size_t)MPAD * HDIM];
__device__ float g_o1[N_NODES * 2];
__device__ float g_o2[N_NODES * 2];
__device__ float g_sort[SORT_N];
__device__ int   g_cnt[N_NODES];
__device__ int   g_rowptr[N_NODES + 1];
__device__ int   g_cursor[N_NODES];
__device__ int   g_esrc[N_EDGES];

// ---------------- helpers ----------------
__device__ __forceinline__ void split1(float v, uint32_t& h, uint32_t& l) {
    uint32_t hu; asm("cvt.rna.tf32.f32 %0, %1;" : "=r"(hu) : "f"(v));
    float lf = v - __uint_as_float(hu);
    uint32_t lu; asm("cvt.rna.tf32.f32 %0, %1;" : "=r"(lu) : "f"(lf));
    h = hu; l = lu;
}
__device__ __forceinline__ void mma_tf32(float* c, const uint32_t* a, const uint32_t* b) {
    asm volatile(
        "mma.sync.aligned.m16n8k8.row.col.f32.tf32.tf32.f32 "
        "{%0,%1,%2,%3}, {%4,%5,%6,%7}, {%8,%9}, {%0,%1,%2,%3};"
        : "+f"(c[0]), "+f"(c[1]), "+f"(c[2]), "+f"(c[3])
        : "r"(a[0]), "r"(a[1]), "r"(a[2]), "r"(a[3]), "r"(b[0]), "r"(b[1]));
}

// ---------------- CSR build ----------------
__global__ void k_zero_cnt() {
    int i = blockIdx.x * blockDim.x + threadIdx.x;
    if (i < N_NODES) g_cnt[i] = 0;
}
__global__ void k_hist(const int* __restrict__ dst) {
    int e = blockIdx.x * blockDim.x + threadIdx.x;
    if (e < N_EDGES) atomicAdd(&g_cnt[dst[e]], 1);
}
__global__ void k_scan() {
    __shared__ int s[1024];
    __shared__ int carry;
    int t = threadIdx.x;
    if (t == 0) carry = 0;
    __syncthreads();
    for (int base = 0; base < N_NODES; base += 1024) {
        int v = (base + t < N_NODES) ? g_cnt[base + t] : 0;
        s[t] = v;
        __syncthreads();
        for (int off = 1; off < 1024; off <<= 1) {
            int a = (t >= off) ? s[t - off] : 0;
            __syncthreads();
            s[t] += a;
            __syncthreads();
        }
        int exc = s[t] - v + carry;
        if (base + t < N_NODES) { g_rowptr[base + t] = exc; g_cursor[base + t] = exc; }
        __syncthreads();
        if (t == 0) carry = carry + s[1023];
        __syncthreads();
    }
    if (t == 0) g_rowptr[N_NODES] = carry;
}
__global__ void k_fill(const int* __restrict__ src, const int* __restrict__ dst) {
    int e = blockIdx.x * blockDim.x + threadIdx.x;
    if (e < N_EDGES) {
        int d = dst[e];
        int pos = atomicAdd(&g_cursor[d], 1);
        g_esrc[pos] = src[e];
    }
}

// ---------------- aggregation: out[i] = x[i] + sum_{j->i} x[j] ----------------
template <int F>
__global__ void k_agg(const float* __restrict__ x, float* __restrict__ out) {
    const int FV = F / 4;
    int node = blockIdx.x;
    int t = threadIdx.x;
    __shared__ int ssrc[256];
    const float4* x4 = (const float4*)x;
    float4 acc = x4[(size_t)node * FV + t];
    int beg = g_rowptr[node], end = g_rowptr[node + 1];
    for (int c = beg; c < end; c += 256) {
        int m = min(256, end - c);
        for (int i = t; i < m; i += FV) ssrc[i] = g_esrc[c + i];
        __syncthreads();
        for (int i = 0; i < m; i++) {
            float4 v = x4[(size_t)ssrc[i] * FV + t];
            acc.x += v.x; acc.y += v.y; acc.z += v.z; acc.w += v.w;
        }
        __syncthreads();
    }
    ((float4*)out)[(size_t)node * FV + t] = acc;
}

// ---------------- 3xTF32 mma.sync GEMM: C[MPAD,512] = relu(A[MPAD,K] @ W[K,512] + b)
// Block 128x128x16, 256 thr, 8 warps (4x2), warp tile 32x64 (2 m16 x 8 n8).
// smem: per stage Ah/Al [16][136] (k-major, m contiguous across rows? no: [k][m]),
//       Bh/Bl [16][136] ([k][n] = native W layout). stride 136 -> conflict-free frags.
#define GSTRIDE 136
#define GMATF   (16 * GSTRIDE)           // floats per matrix
#define GSMEM   (8 * GMATF * 4)          // 2 stages * 4 matrices, bytes = 69632
#define SM_OFF(s, mat) (((s) * 4 + (mat)) * GMATF)

__global__ void __launch_bounds__(256)
k_gemm_mma(const float* __restrict__ A, const float* __restrict__ W,
           const float* __restrict__ bias, float* __restrict__ C, int K) {
    extern __shared__ uint32_t S[];
    int t = threadIdx.x, lane = t & 31, wid = t >> 5;
    int warp_m = wid >> 1, warp_n = wid & 1;
    int rowBase = blockIdx.y * 128;
    int colBase = blockIdx.x * 128;

    float acc[2][8][4];
#pragma unroll
    for (int i = 0; i < 2; i++)
#pragma unroll
        for (int j = 0; j < 8; j++)
#pragma unroll
            for (int q = 0; q < 4; q++) acc[i][j][q] = 0.f;

    // global load mapping
    int a_row = t >> 1;                 // 0..127
    int a_k0 = (t & 1) * 8;             // 0 or 8; loads k0..k0+3 and k0+4..k0+7
    int b_krow = t >> 4;                // 0..15
    int b_n0 = (t & 15) * 4;            // two float4 at n0 and n0+64

    const float* Ap = A + (size_t)(rowBase + a_row) * K + a_k0;
    const float* Bp = W + (size_t)b_krow * HDIM + colBase + b_n0;

    const int nk = K >> 4;
    float4 ra0, ra1, rb0, rb1;

    // prologue: load stage 0
    ra0 = *(const float4*)(Ap);
    ra1 = *(const float4*)(Ap + 4);
    rb0 = *(const float4*)(Bp);
    rb1 = *(const float4*)(Bp + 64);

    for (int s = 0; s < nk; s++) {
        int buf = s & 1;
        uint32_t* Ah = S + SM_OFF(buf, 0);
        uint32_t* Al = S + SM_OFF(buf, 1);
        uint32_t* Bh = S + SM_OFF(buf, 2);
        uint32_t* Bl = S + SM_OFF(buf, 3);
        // store regs -> smem with hi/lo split
        {
            uint32_t h, l;
            float av[8] = {ra0.x, ra0.y, ra0.z, ra0.w, ra1.x, ra1.y, ra1.z, ra1.w};
#pragma unroll
            for (int i = 0; i < 8; i++) {
                split1(av[i], h, l);
                int idx = (a_k0 + i) * GSTRIDE + a_row;
                Ah[idx] = h; Al[idx] = l;
            }
            uint4 hh, ll;
            split1(rb0.x, hh.x, ll.x); split1(rb0.y, hh.y, ll.y);
            split1(rb0.z, hh.z, ll.z); split1(rb0.w, hh.w, ll.w);
            *(uint4*)&Bh[b_krow * GSTRIDE + b_n0] = hh;
            *(uint4*)&Bl[b_krow * GSTRIDE + b_n0] = ll;
            split1(rb1.x, hh.x, ll.x); split1(rb1.y, hh.y, ll.y);
            split1(rb1.z, hh.z, ll.z); split1(rb1.w, hh.w, ll.w);
            *(uint4*)&Bh[b_krow * GSTRIDE + b_n0 + 64] = hh;
            *(uint4*)&Bl[b_krow * GSTRIDE + b_n0 + 64] = ll;
        }
        __syncthreads();
        // prefetch next stage
        if (s + 1 < nk) {
            const float* Ap2 = Ap + (s + 1) * 16;
            const float* Bp2 = Bp + (size_t)(s + 1) * 16 * HDIM;
            ra0 = *(const float4*)(Ap2);
            ra1 = *(const float4*)(Ap2 + 4);
            rb0 = *(const float4*)(Bp2);
            rb1 = *(const float4*)(Bp2 + 64);
        }
        // compute on current buffer: 2 k8 steps
#pragma unroll
        for (int kk = 0; kk < 2; kk++) {
            int kb = kk * 8 + (lane & 3);
            int g = lane >> 2;
            uint32_t bhf[8][2], blf[8][2];
#pragma unroll
            for (int nt = 0; nt < 8; nt++) {
                int n = warp_n * 64 + nt * 8 + g;
                bhf[nt][0] = Bh[kb * GSTRIDE + n];
                bhf[nt][1] = Bh[(kb + 4) * GSTRIDE + n];
                blf[nt][0] = Bl[kb * GSTRIDE + n];
                blf[nt][1] = Bl[(kb + 4) * GSTRIDE + n];
            }
#pragma unroll
            for (int mt = 0; mt < 2; mt++) {
                int m = warp_m * 32 + mt * 16 + g;
                uint32_t ahf[4], alf[4];
                ahf[0] = Ah[kb * GSTRIDE + m];
                ahf[1] = Ah[kb * GSTRIDE + m + 8];
                ahf[2] = Ah[(kb + 4) * GSTRIDE + m];
                ahf[3] = Ah[(kb + 4) * GSTRIDE + m + 8];
                alf[0] = Al[kb * GSTRIDE + m];
                alf[1] = Al[kb * GSTRIDE + m + 8];
                alf[2] = Al[(kb + 4) * GSTRIDE + m];
                alf[3] = Al[(kb + 4) * GSTRIDE + m + 8];
#pragma unroll
                for (int nt = 0; nt < 8; nt++) {
                    mma_tf32(acc[mt][nt], ahf, bhf[nt]);
                    mma_tf32(acc[mt][nt], alf, bhf[nt]);
                    mma_tf32(acc[mt][nt], ahf, blf[nt]);
                }
            }
        }
        __syncthreads();
    }

    // epilogue: bias + relu, write C
    int g = lane >> 2;
    int cq = (lane & 3) * 2;
#pragma unroll
    for (int mt = 0; mt < 2; mt++) {
        int row = rowBase + warp_m * 32 + mt * 16 + g;
#pragma unroll
        for (int nt = 0; nt < 8; nt++) {
            int col = colBase + warp_n * 64 + nt * 8 + cq;
            float b0 = bias[col], b1 = bias[col + 1];
            float2 o0, o1;
            o0.x = fmaxf(acc[mt][nt][0] + b0, 0.f);
            o0.y = fmaxf(acc[mt][nt][1] + b1, 0.f);
            o1.x = fmaxf(acc[mt][nt][2] + b0, 0.f);
            o1.y = fmaxf(acc[mt][nt][3] + b1, 0.f);
            *(float2*)&C[(size_t)row * HDIM + col] = o0;
            *(float2*)&C[(size_t)(row + 8) * HDIM + col] = o1;
        }
    }
}

// ---------------- final linear [N,512] @ [512,2] ----------------
__global__ void k_lin(const float* __restrict__ act, const float* __restrict__ w,
                      const float* __restrict__ b, float* __restrict__ o) {
    int warp = (blockIdx.x * blockDim.x + threadIdx.x) >> 5;
    int lane = threadIdx.x & 31;
    if (warp >= N_NODES) return;
    float a0 = 0.f, a1 = 0.f;
    for (int k = lane; k < HDIM; k += 32) {
        float v = act[(size_t)warp * HDIM + k];
        a0 += v * w[k * 2];
        a1 += v * w[k * 2 + 1];
    }
#pragma unroll
    for (int off = 16; off; off >>= 1) {
        a0 += __shfl_down_sync(0xffffffffu, a0, off);
        a1 += __shfl_down_sync(0xffffffffu, a1, off);
    }
    if (lane == 0) {
        o[warp * 2]     = a0 + b[0];
        o[warp * 2 + 1] = a1 + b[1];
    }
}

// ---------------- pairwise distance + pad ----------------
__global__ void k_dist() {
    int i = blockIdx.x * blockDim.x + threadIdx.x;
    if (i >= SORT_N) return;
    if (i < N_NODES) {
        float dx = g_o1[i * 2]     - g_o2[i * 2]     + 1e-6f;
        float dy = g_o1[i * 2 + 1] - g_o2[i * 2 + 1] + 1e-6f;
        g_sort[i] = sqrtf(dx * dx + dy * dy);
    } else {
        g_sort[i] = -INFINITY;
    }
}

// ---------------- single-block bitonic sort (descending) ----------------
__global__ void k_sort() {
    extern __shared__ float s[];
    int t = threadIdx.x;
    for (int i = t; i < SORT_N; i += 1024) s[i] = g_sort[i];
    __syncthreads();
    for (int k = 2; k <= SORT_N; k <<= 1) {
        for (int j = k >> 1; j > 0; j >>= 1) {
            for (int i = t; i < SORT_N; i += 1024) {
                int ixj = i ^ j;
                if (ixj > i) {
                    bool dsc = (i & k) == 0;
                    float a = s[i], c = s[ixj];
                    bool sw = dsc ? (a < c) : (a > c);
                    if (sw) { s[i] = c; s[ixj] = a; }
                }
            }
            __syncthreads();
        }
    }
    for (int i = t; i < TOPK; i += 1024) g_sort[i] = s[i];
}

// ---------------- head MLP (single block, 512 threads) ----------------
__global__ void k_mlp(const float* __restrict__ fc1w, const float* __restrict__ fc1b,
                      const float* __restrict__ ln1g, const float* __restrict__ ln1b,
                      const float* __restrict__ fc2w, const float* __restrict__ fc2b,
                      const float* __restrict__ ln2g, const float* __restrict__ ln2b,
                      const float* __restrict__ fc3w, const float* __restrict__ fc3b,
                      float* __restrict__ out) {
    __shared__ float vals[TOPK];
    __shared__ float h1[128];
    __shared__ float part[4][128];
    __shared__ float h2[512];
    __shared__ float red[512];
    int t = threadIdx.x;
    for (int i = t; i < TOPK; i += 512) vals[i] = g_sort[i];
    __syncthreads();
    {
        int j = t & 127, c = t >> 7;
        float acc = 0.f;
        for (int i = c * 250; i < (c + 1) * 250; i++) acc += vals[i] * fc1w[i * 128 + j];
        part[c][j] = acc;
    }
    __syncthreads();
    if (t < 128) h1[t] = part[0][t] + part[1][t] + part[2][t] + part[3][t] + fc1b[t];
    __syncthreads();
    red[t] = (t < 128) ? h1[t] : 0.f;
    __syncthreads();
    for (int off = 256; off; off >>= 1) { if (t < off) red[t] += red[t + off]; __syncthreads(); }
    float mean1 = red[0] / 128.f;
    __syncthreads();
    red[t] = (t < 128) ? (h1[t] - mean1) * (h1[t] - mean1) : 0.f;
    __syncthreads();
    for (int off = 256; off; off >>= 1) { if (t < off) red[t] += red[t + off]; __syncthreads(); }
    float var1 = red[0] / 128.f;
    __syncthreads();
    if (t < 128) {
        float v = (h1[t] - mean1) * rsqrtf(var1 + 1e-5f) * ln1g[t] + ln1b[t];
        h1[t] = fmaxf(v, 0.f);
    }
    __syncthreads();
    {
        float acc = fc2b[t];
        for (int i = 0; i < 128; i++) acc += h1[i] * fc2w[i * 512 + t];
        h2[t] = acc;
    }
    __syncthreads();
    red[t] = h2[t];
    __syncthreads();
    for (int off = 256; off; off >>= 1) { if (t < off) red[t] += red[t + off]; __syncthreads(); }
    float mean2 = red[0] / 512.f;
    __syncthreads();
    red[t] = (h2[t] - mean2) * (h2[t] - mean2);
    __syncthreads();
    for (int off = 256; off; off >>= 1) { if (t < off) red[t] += red[t + off]; __syncthreads(); }
    float var2 = red[0] / 512.f;
    __syncthreads();
    float hr = fmaxf((h2[t] - mean2) * rsqrtf(var2 + 1e-5f) * ln2g[t] + ln2b[t], 0.f);
    red[t] = hr * fc3w[t];
    __syncthreads();
    for (int off = 256; off; off >>= 1) { if (t < off) red[t] += red[t + off]; __syncthreads(); }
    if (t == 0) out[0] = 1.f / (1.f + expf(-(red[0] + fc3b[0])));
}

// ---------------- launch ----------------
extern "C" void kernel_launch(void* const* d_in, const int* in_sizes, int n_in,
                              void* d_out, int out_size) {
    const float* x1   = (const float*)d_in[0];
    const int*   ei1  = (const int*)d_in[1];
    const float* x2   = (const float*)d_in[2];
    const int*   ei2  = (const int*)d_in[3];
    const float* w11  = (const float*)d_in[4];
    const float* b11  = (const float*)d_in[5];
    const float* w12  = (const float*)d_in[6];
    const float* b12  = (const float*)d_in[7];
    const float* w21  = (const float*)d_in[8];
    const float* b21  = (const float*)d_in[9];
    const float* w22  = (const float*)d_in[10];
    const float* b22  = (const float*)d_in[11];
    const float* w31  = (const float*)d_in[12];
    const float* b31  = (const float*)d_in[13];
    const float* w32  = (const float*)d_in[14];
    const float* b32  = (const float*)d_in[15];
    const float* linw = (const float*)d_in[16];
    const float* linb = (const float*)d_in[17];
    const float* fc1w = (const float*)d_in[18];
    const float* fc1b = (const float*)d_in[19];
    const float* ln1g = (const float*)d_in[20];
    const float* ln1b = (const float*)d_in[21];
    const float* fc2w = (const float*)d_in[22];
    const float* fc2b = (const float*)d_in[23];
    const float* ln2g = (const float*)d_in[24];
    const float* ln2b = (const float*)d_in[25];
    const float* fc3w = (const float*)d_in[26];
    const float* fc3b = (const float*)d_in[27];
    float* out = (float*)d_out;

    float *p_agg, *p_tmp, *p_act, *p_o1, *p_o2;
    cudaGetSymbolAddress((void**)&p_agg, g_agg);
    cudaGetSymbolAddress((void**)&p_tmp, g_tmp);
    cudaGetSymbolAddress((void**)&p_act, g_act);
    cudaGetSymbolAddress((void**)&p_o1, g_o1);
    cudaGetSymbolAddress((void**)&p_o2, g_o2);

    cudaFuncSetAttribute(k_sort, cudaFuncAttributeMaxDynamicSharedMemorySize, SORT_N * 4);
    cudaFuncSetAttribute(k_gemm_mma, cudaFuncAttributeMaxDynamicSharedMemorySize, GSMEM);

    dim3 ggrid(HDIM / 128, MT);
    const int EB = (N_EDGES + 255) / 256;
    const int NB = (N_NODES + 255) / 256;

    for (int g = 0; g < 2; g++) {
        const float* x   = g ? x2 : x1;
        const int*   src = g ? ei2 : ei1;
        const int*   dst = src + N_EDGES;
        float*       o   = g ? p_o2 : p_o1;

        k_zero_cnt<<<NB, 256>>>();
        k_hist<<<EB, 256>>>(dst);
        k_scan<<<1, 1024>>>();
        k_fill<<<EB, 256>>>(src, dst);

        // layer 1 (FIN=256 -> H)
        k_agg<FIN_DIM><<<N_NODES, FIN_DIM / 4>>>(x, p_agg);
        k_gemm_mma<<<ggrid, 256, GSMEM>>>(p_agg, w11, b11, p_tmp, FIN_DIM);
        k_gemm_mma<<<ggrid, 256, GSMEM>>>(p_tmp, w12, b12, p_act, HDIM);
        // layer 2
        k_agg<HDIM><<<N_NODES, HDIM / 4>>>(p_act, p_agg);
        k_gemm_mma<<<ggrid, 256, GSMEM>>>(p_agg, w21, b21, p_tmp, HDIM);
        k_gemm_mma<<<ggrid, 256, GSMEM>>>(p_tmp, w22, b22, p_act, HDIM);
        // layer 3
        k_agg<HDIM><<<N_NODES, HDIM / 4>>>(p_act, p_agg);
        k_gemm_mma<<<ggrid, 256, GSMEM>>>(p_agg, w31, b31, p_tmp, HDIM);
        k_gemm_mma<<<ggrid, 256, GSMEM>>>(p_tmp, w32, b32, p_act, HDIM);
        // lin head -> [N,2]
        k_lin<<<(N_NODES * 32 + 255) / 256, 256>>>(p_act, linw, linb, o);
    }

    k_dist<<<SORT_N / 256, 256>>>();
    k_sort<<<1, 1024, SORT_N * 4>>>();
    k_mlp<<<1, 512>>>(fc1w, fc1b, ln1g, ln1b, fc2w, fc2b, ln2g, ln2b, fc3w, fc3b, out);
}

// round 4
// speedup vs baseline: 1.7516x; 1.4574x over previous
#include <cuda_runtime.h>
#include <math.h>
#include <stdint.h>

#define N_NODES 20000
#define MPAD    20096
#define MT      157
#define N_EDGES 640000
#define FIN_DIM 256
#define HDIM 512
#define TOPK 1000
#define SELN 4096

// ---------------- scratch (static device memory; no allocations) ----------------
__device__ float g_agg[(size_t)MPAD * HDIM];
__device__ float g_tmp[(size_t)MPAD * HDIM];
__device__ float g_act[(size_t)MPAD * HDIM];
__device__ float g_o1[N_NODES * 2];
__device__ float g_o2[N_NODES * 2];
__device__ float g_dist[N_NODES];
__device__ float g_sel[SELN];
__device__ float g_top[TOPK];
__device__ int   g_selcnt;
__device__ int   g_thrbin;
__device__ int   g_cnt[N_NODES];
__device__ int   g_rowptr[N_NODES + 1];
__device__ int   g_cursor[N_NODES];
__device__ int   g_esrc[N_EDGES];

// ---------------- helpers ----------------
__device__ __forceinline__ uint32_t packbf(float lo_e, float hi_o) {
    uint32_t r;
    asm("cvt.rn.bf16x2.f32 %0, %1, %2;" : "=r"(r) : "f"(hi_o), "f"(lo_e));
    return r;  // lo 16 bits = lo_e (k even), hi = hi_o (k odd)
}
// split a k-pair (v0=k even, v1=k odd) into hi/lo packed bf16x2 words
__device__ __forceinline__ void split2(float v0, float v1, uint32_t& h, uint32_t& l) {
    h = packbf(v0, v1);
    float h0 = __uint_as_float(h << 16);
    float h1 = __uint_as_float(h & 0xffff0000u);
    l = packbf(v0 - h0, v1 - h1);
}
__device__ __forceinline__ void mma_bf16(float* c, const uint32_t* a, const uint32_t* b) {
    asm volatile(
        "mma.sync.aligned.m16n8k16.row.col.f32.bf16.bf16.f32 "
        "{%0,%1,%2,%3}, {%4,%5,%6,%7}, {%8,%9}, {%0,%1,%2,%3};"
        : "+f"(c[0]), "+f"(c[1]), "+f"(c[2]), "+f"(c[3])
        : "r"(a[0]), "r"(a[1]), "r"(a[2]), "r"(a[3]), "r"(b[0]), "r"(b[1]));
}

// ---------------- CSR build ----------------
__global__ void k_zero_cnt() {
    int i = blockIdx.x * blockDim.x + threadIdx.x;
    if (i < N_NODES) g_cnt[i] = 0;
}
__global__ void k_hist(const int* __restrict__ dst) {
    int e = blockIdx.x * blockDim.x + threadIdx.x;
    if (e < N_EDGES) atomicAdd(&g_cnt[dst[e]], 1);
}
__global__ void k_scan() {
    __shared__ int s[1024];
    __shared__ int carry;
    int t = threadIdx.x;
    if (t == 0) carry = 0;
    __syncthreads();
    for (int base = 0; base < N_NODES; base += 1024) {
        int v = (base + t < N_NODES) ? g_cnt[base + t] : 0;
        s[t] = v;
        __syncthreads();
        for (int off = 1; off < 1024; off <<= 1) {
            int a = (t >= off) ? s[t - off] : 0;
            __syncthreads();
            s[t] += a;
            __syncthreads();
        }
        int exc = s[t] - v + carry;
        if (base + t < N_NODES) { g_rowptr[base + t] = exc; g_cursor[base + t] = exc; }
        __syncthreads();
        if (t == 0) carry = carry + s[1023];
        __syncthreads();
    }
    if (t == 0) g_rowptr[N_NODES] = carry;
}
__global__ void k_fill(const int* __restrict__ src, const int* __restrict__ dst) {
    int e = blockIdx.x * blockDim.x + threadIdx.x;
    if (e < N_EDGES) {
        int d = dst[e];
        int pos = atomicAdd(&g_cursor[d], 1);
        g_esrc[pos] = src[e];
    }
}

// ---------------- aggregation: out[i] = x[i] + sum_{j->i} x[j] ----------------
template <int F>
__global__ void k_agg(const float* __restrict__ x, float* __restrict__ out) {
    const int FV = F / 4;
    int node = blockIdx.x;
    int t = threadIdx.x;
    __shared__ int ssrc[256];
    const float4* x4 = (const float4*)x;
    float4 acc = x4[(size_t)node * FV + t];
    int beg = g_rowptr[node], end = g_rowptr[node + 1];
    for (int c = beg; c < end; c += 256) {
        int m = min(256, end - c);
        for (int i = t; i < m; i += FV) ssrc[i] = g_esrc[c + i];
        __syncthreads();
        for (int i = 0; i < m; i++) {
            float4 v = x4[(size_t)ssrc[i] * FV + t];
            acc.x += v.x; acc.y += v.y; acc.z += v.z; acc.w += v.w;
        }
        __syncthreads();
    }
    ((float4*)out)[(size_t)node * FV + t] = acc;
}

// ---------------- 3x-bf16 mma.sync GEMM: C[MPAD,512] = relu(A[MPAD,K] @ W[K,512] + b)
// Block 128x128x16, 256 thr, 8 warps (4x2), warp tile 32x64.
// smem: per stage Ah/Al/Bh/Bl as [k2(8)][stride 140] packed bf16x2 words.
#define GSTRIDE 140
#define GMATW   (8 * GSTRIDE)

__global__ void __launch_bounds__(256)
k_gemm_mma(const float* __restrict__ A, const float* __restrict__ W,
           const float* __restrict__ bias, float* __restrict__ C, int K) {
    __shared__ uint32_t S[2][4][GMATW];
    int t = threadIdx.x, lane = t & 31, wid = t >> 5;
    int warp_m = wid >> 1, warp_n = wid & 1;
    int rowBase = blockIdx.y * 128;
    int colBase = blockIdx.x * 128;

    float acc[2][8][4];
#pragma unroll
    for (int i = 0; i < 2; i++)
#pragma unroll
        for (int j = 0; j < 8; j++)
#pragma unroll
            for (int q = 0; q < 4; q++) acc[i][j][q] = 0.f;

    // global load mapping
    int a_row = t >> 1;               // 0..127
    int a_half = t & 1;               // k offset 0 or 8
    int b_k2 = t >> 5;                // 0..7 (k pair row)
    int b_n0 = (lane) * 4;            // 4 consecutive n

    const float* Ap = A + (size_t)(rowBase + a_row) * K + a_half * 8;
    const float* Bp0 = W + (size_t)(2 * b_k2) * HDIM + colBase + b_n0;
    const float* Bp1 = Bp0 + HDIM;

    const int nk = K >> 4;
    float4 ra0, ra1, rb0, rb1;

    ra0 = *(const float4*)(Ap);
    ra1 = *(const float4*)(Ap + 4);
    rb0 = *(const float4*)(Bp0);
    rb1 = *(const float4*)(Bp1);

    for (int s = 0; s < nk; s++) {
        int buf = s & 1;
        uint32_t* Ah = S[buf][0];
        uint32_t* Al = S[buf][1];
        uint32_t* Bh = S[buf][2];
        uint32_t* Bl = S[buf][3];
        // convert + store
        {
            float av[8] = {ra0.x, ra0.y, ra0.z, ra0.w, ra1.x, ra1.y, ra1.z, ra1.w};
#pragma unroll
            for (int i = 0; i < 4; i++) {
                uint32_t h, l;
                split2(av[2 * i], av[2 * i + 1], h, l);
                int idx = (a_half * 4 + i) * GSTRIDE + a_row;
                Ah[idx] = h; Al[idx] = l;
            }
            uint4 hh, ll;
            split2(rb0.x, rb1.x, hh.x, ll.x);
            split2(rb0.y, rb1.y, hh.y, ll.y);
            split2(rb0.z, rb1.z, hh.z, ll.z);
            split2(rb0.w, rb1.w, hh.w, ll.w);
            *(uint4*)&Bh[b_k2 * GSTRIDE + b_n0] = hh;
            *(uint4*)&Bl[b_k2 * GSTRIDE + b_n0] = ll;
        }
        __syncthreads();
        // prefetch next stage
        if (s + 1 < nk) {
            const float* Ap2 = Ap + (s + 1) * 16;
            const float* Bp2 = Bp0 + (size_t)(s + 1) * 16 * HDIM;
            ra0 = *(const float4*)(Ap2);
            ra1 = *(const float4*)(Ap2 + 4);
            rb0 = *(const float4*)(Bp2);
            rb1 = *(const float4*)(Bp2 + HDIM);
        }
        // compute: one k16 step
        {
            int g = lane >> 2, q = lane & 3;
            uint32_t bhf[8][2], blf[8][2];
#pragma unroll
            for (int nt = 0; nt < 8; nt++) {
                int n = warp_n * 64 + nt * 8 + g;
                bhf[nt][0] = Bh[q * GSTRIDE + n];
                bhf[nt][1] = Bh[(q + 4) * GSTRIDE + n];
                blf[nt][0] = Bl[q * GSTRIDE + n];
                blf[nt][1] = Bl[(q + 4) * GSTRIDE + n];
            }
#pragma unroll
            for (int mt = 0; mt < 2; mt++) {
                int m = warp_m * 32 + mt * 16 + g;
                uint32_t ahf[4], alf[4];
                ahf[0] = Ah[q * GSTRIDE + m];
                ahf[1] = Ah[q * GSTRIDE + m + 8];
                ahf[2] = Ah[(q + 4) * GSTRIDE + m];
                ahf[3] = Ah[(q + 4) * GSTRIDE + m + 8];
                alf[0] = Al[q * GSTRIDE + m];
                alf[1] = Al[q * GSTRIDE + m + 8];
                alf[2] = Al[(q + 4) * GSTRIDE + m];
                alf[3] = Al[(q + 4) * GSTRIDE + m + 8];
#pragma unroll
                for (int nt = 0; nt < 8; nt++) {
                    mma_bf16(acc[mt][nt], ahf, bhf[nt]);
                    mma_bf16(acc[mt][nt], alf, bhf[nt]);
                    mma_bf16(acc[mt][nt], ahf, blf[nt]);
                }
            }
        }
        __syncthreads();
    }

    // epilogue
    int g = lane >> 2;
    int cq = (lane & 3) * 2;
#pragma unroll
    for (int mt = 0; mt < 2; mt++) {
        int row = rowBase + warp_m * 32 + mt * 16 + g;
#pragma unroll
        for (int nt = 0; nt < 8; nt++) {
            int col = colBase + warp_n * 64 + nt * 8 + cq;
            float b0 = bias[col], b1 = bias[col + 1];
            float2 o0, o1;
            o0.x = fmaxf(acc[mt][nt][0] + b0, 0.f);
            o0.y = fmaxf(acc[mt][nt][1] + b1, 0.f);
            o1.x = fmaxf(acc[mt][nt][2] + b0, 0.f);
            o1.y = fmaxf(acc[mt][nt][3] + b1, 0.f);
            *(float2*)&C[(size_t)row * HDIM + col] = o0;
            *(float2*)&C[(size_t)(row + 8) * HDIM + col] = o1;
        }
    }
}

// ---------------- final linear [N,512] @ [512,2] ----------------
__global__ void k_lin(const float* __restrict__ act, const float* __restrict__ w,
                      const float* __restrict__ b, float* __restrict__ o) {
    int warp = (blockIdx.x * blockDim.x + threadIdx.x) >> 5;
    int lane = threadIdx.x & 31;
    if (warp >= N_NODES) return;
    float a0 = 0.f, a1 = 0.f;
    for (int k = lane; k < HDIM; k += 32) {
        float v = act[(size_t)warp * HDIM + k];
        a0 += v * w[k * 2];
        a1 += v * w[k * 2 + 1];
    }
#pragma unroll
    for (int off = 16; off; off >>= 1) {
        a0 += __shfl_down_sync(0xffffffffu, a0, off);
        a1 += __shfl_down_sync(0xffffffffu, a1, off);
    }
    if (lane == 0) {
        o[warp * 2]     = a0 + b[0];
        o[warp * 2 + 1] = a1 + b[1];
    }
}

// ---------------- pairwise distance ----------------
__global__ void k_dist() {
    int i = blockIdx.x * blockDim.x + threadIdx.x;
    if (i >= N_NODES) return;
    float dx = g_o1[i * 2]     - g_o2[i * 2]     + 1e-6f;
    float dy = g_o1[i * 2 + 1] - g_o2[i * 2 + 1] + 1e-6f;
    g_dist[i] = sqrtf(dx * dx + dy * dy);
}

// ---------------- top-k select: histogram threshold ----------------
__global__ void k_selhist() {
    __shared__ int hist[2048];
    int t = threadIdx.x;  // 1024 threads, 1 block
    hist[t] = 0; hist[t + 1024] = 0;
    // init selection buffer
    for (int i = t; i < SELN; i += 1024) g_sel[i] = -INFINITY;
    if (t == 0) g_selcnt = 0;
    __syncthreads();
    for (int i = t; i < N_NODES; i += 1024) {
        uint32_t bits = __float_as_uint(g_dist[i]);
        atomicAdd(&hist[bits >> 21], 1);
    }
    __syncthreads();
    if (t == 0) {
        int cum = 0, thr = 0;
        for (int b = 2047; b >= 0; b--) {
            cum += hist[b];
            if (cum >= TOPK) { thr = b; break; }
        }
        g_thrbin = thr;
    }
}
__global__ void k_compact() {
    int i = blockIdx.x * blockDim.x + threadIdx.x;
    if (i >= N_NODES) return;
    float d = g_dist[i];
    if ((int)(__float_as_uint(d) >> 21) >= g_thrbin) {
        int pos = atomicAdd(&g_selcnt, 1);
        if (pos < SELN) g_sel[pos] = d;
    }
}
// bitonic sort 4096 descending, emit top 1000
__global__ void k_sortsel() {
    __shared__ float s[SELN];
    int t = threadIdx.x;  // 1024
    for (int i = t; i < SELN; i += 1024) s[i] = g_sel[i];
    __syncthreads();
    for (int k = 2; k <= SELN; k <<= 1) {
        for (int j = k >> 1; j > 0; j >>= 1) {
            for (int i = t; i < SELN; i += 1024) {
                int ixj = i ^ j;
                if (ixj > i) {
                    bool dsc = (i & k) == 0;
                    float a = s[i], c = s[ixj];
                    bool sw = dsc ? (a < c) : (a > c);
                    if (sw) { s[i] = c; s[ixj] = a; }
                }
            }
            __syncthreads();
        }
    }
    for (int i = t; i < TOPK; i += 1024) g_top[i] = s[i];
}

// ---------------- head MLP (single block, 512 threads) ----------------
__global__ void k_mlp(const float* __restrict__ fc1w, const float* __restrict__ fc1b,
                      const float* __restrict__ ln1g, const float* __restrict__ ln1b,
                      const float* __restrict__ fc2w, const float* __restrict__ fc2b,
                      const float* __restrict__ ln2g, const float* __restrict__ ln2b,
                      const float* __restrict__ fc3w, const float* __restrict__ fc3b,
                      float* __restrict__ out) {
    __shared__ float vals[TOPK];
    __shared__ float h1[128];
    __shared__ float part[4][128];
    __shared__ float h2[512];
    __shared__ float red[512];
    int t = threadIdx.x;
    for (int i = t; i < TOPK; i += 512) vals[i] = g_top[i];
    __syncthreads();
    {
        int j = t & 127, c = t >> 7;
        float acc = 0.f;
        for (int i = c * 250; i < (c + 1) * 250; i++) acc += vals[i] * fc1w[i * 128 + j];
        part[c][j] = acc;
    }
    __syncthreads();
    if (t < 128) h1[t] = part[0][t] + part[1][t] + part[2][t] + part[3][t] + fc1b[t];
    __syncthreads();
    red[t] = (t < 128) ? h1[t] : 0.f;
    __syncthreads();
    for (int off = 256; off; off >>= 1) { if (t < off) red[t] += red[t + off]; __syncthreads(); }
    float mean1 = red[0] / 128.f;
    __syncthreads();
    red[t] = (t < 128) ? (h1[t] - mean1) * (h1[t] - mean1) : 0.f;
    __syncthreads();
    for (int off = 256; off; off >>= 1) { if (t < off) red[t] += red[t + off]; __syncthreads(); }
    float var1 = red[0] / 128.f;
    __syncthreads();
    if (t < 128) {
        float v = (h1[t] - mean1) * rsqrtf(var1 + 1e-5f) * ln1g[t] + ln1b[t];
        h1[t] = fmaxf(v, 0.f);
    }
    __syncthreads();
    {
        float acc = fc2b[t];
        for (int i = 0; i < 128; i++) acc += h1[i] * fc2w[i * 512 + t];
        h2[t] = acc;
    }
    __syncthreads();
    red[t] = h2[t];
    __syncthreads();
    for (int off = 256; off; off >>= 1) { if (t < off) red[t] += red[t + off]; __syncthreads(); }
    float mean2 = red[0] / 512.f;
    __syncthreads();
    red[t] = (h2[t] - mean2) * (h2[t] - mean2);
    __syncthreads();
    for (int off = 256; off; off >>= 1) { if (t < off) red[t] += red[t + off]; __syncthreads(); }
    float var2 = red[0] / 512.f;
    __syncthreads();
    float hr = fmaxf((h2[t] - mean2) * rsqrtf(var2 + 1e-5f) * ln2g[t] + ln2b[t], 0.f);
    red[t] = hr * fc3w[t];
    __syncthreads();
    for (int off = 256; off; off >>= 1) { if (t < off) red[t] += red[t + off]; __syncthreads(); }
    if (t == 0) out[0] = 1.f / (1.f + expf(-(red[0] + fc3b[0])));
}

// ---------------- launch ----------------
extern "C" void kernel_launch(void* const* d_in, const int* in_sizes, int n_in,
                              void* d_out, int out_size) {
    const float* x1   = (const float*)d_in[0];
    const int*   ei1  = (const int*)d_in[1];
    const float* x2   = (const float*)d_in[2];
    const int*   ei2  = (const int*)d_in[3];
    const float* w11  = (const float*)d_in[4];
    const float* b11  = (const float*)d_in[5];
    const float* w12  = (const float*)d_in[6];
    const float* b12  = (const float*)d_in[7];
    const float* w21  = (const float*)d_in[8];
    const float* b21  = (const float*)d_in[9];
    const float* w22  = (const float*)d_in[10];
    const float* b22  = (const float*)d_in[11];
    const float* w31  = (const float*)d_in[12];
    const float* b31  = (const float*)d_in[13];
    const float* w32  = (const float*)d_in[14];
    const float* b32  = (const float*)d_in[15];
    const float* linw = (const float*)d_in[16];
    const float* linb = (const float*)d_in[17];
    const float* fc1w = (const float*)d_in[18];
    const float* fc1b = (const float*)d_in[19];
    const float* ln1g = (const float*)d_in[20];
    const float* ln1b = (const float*)d_in[21];
    const float* fc2w = (const float*)d_in[22];
    const float* fc2b = (const float*)d_in[23];
    const float* ln2g = (const float*)d_in[24];
    const float* ln2b = (const float*)d_in[25];
    const float* fc3w = (const float*)d_in[26];
    const float* fc3b = (const float*)d_in[27];
    float* out = (float*)d_out;

    float *p_agg, *p_tmp, *p_act, *p_o1, *p_o2;
    cudaGetSymbolAddress((void**)&p_agg, g_agg);
    cudaGetSymbolAddress((void**)&p_tmp, g_tmp);
    cudaGetSymbolAddress((void**)&p_act, g_act);
    cudaGetSymbolAddress((void**)&p_o1, g_o1);
    cudaGetSymbolAddress((void**)&p_o2, g_o2);

    dim3 ggrid(HDIM / 128, MT);
    const int EB = (N_EDGES + 255) / 256;
    const int NB = (N_NODES + 255) / 256;

    for (int g = 0; g < 2; g++) {
        const float* x   = g ? x2 : x1;
        const int*   src = g ? ei2 : ei1;
        const int*   dst = src + N_EDGES;
        float*       o   = g ? p_o2 : p_o1;

        k_zero_cnt<<<NB, 256>>>();
        k_hist<<<EB, 256>>>(dst);
        k_scan<<<1, 1024>>>();
        k_fill<<<EB, 256>>>(src, dst);

        // layer 1 (FIN=256 -> H)
        k_agg<FIN_DIM><<<N_NODES, FIN_DIM / 4>>>(x, p_agg);
        k_gemm_mma<<<ggrid, 256>>>(p_agg, w11, b11, p_tmp, FIN_DIM);
        k_gemm_mma<<<ggrid, 256>>>(p_tmp, w12, b12, p_act, HDIM);
        // layer 2
        k_agg<HDIM><<<N_NODES, HDIM / 4>>>(p_act, p_agg);
        k_gemm_mma<<<ggrid, 256>>>(p_agg, w21, b21, p_tmp, HDIM);
        k_gemm_mma<<<ggrid, 256>>>(p_tmp, w22, b22, p_act, HDIM);
        // layer 3
        k_agg<HDIM><<<N_NODES, HDIM / 4>>>(p_act, p_agg);
        k_gemm_mma<<<ggrid, 256>>>(p_agg, w31, b31, p_tmp, HDIM);
        k_gemm_mma<<<ggrid, 256>>>(p_tmp, w32, b32, p_act, HDIM);
        // lin head -> [N,2]
        k_lin<<<(N_NODES * 32 + 255) / 256, 256>>>(p_act, linw, linb, o);
    }

    k_dist<<<NB, 256>>>();
    k_selhist<<<1, 1024>>>();
    k_compact<<<NB, 256>>>();
    k_sortsel<<<1, 1024>>>();
    k_mlp<<<1, 512>>>(fc1w, fc1b, ln1g, ln1b, fc2w, fc2b, ln2g, ln2b, fc3w, fc3b, out);
}

// round 5
// speedup vs baseline: 1.9606x; 1.1194x over previous
#include <cuda_runtime.h>
#include <math.h>
#include <stdint.h>

#define N_NODES 20000
#define NTOT    40000
#define MPAD2   40192
#define MT2     314
#define N_EDGES 640000
#define FIN_DIM 256
#define HDIM 512
#define TOPK 1000
#define SELN 4096

// ---------------- scratch (static device memory; no allocations) ----------------
__device__ float g_agg[(size_t)MPAD2 * HDIM];
__device__ float g_tmp[(size_t)MPAD2 * HDIM];
__device__ float g_act[(size_t)MPAD2 * HDIM];
__device__ float g_o[NTOT * 2];
__device__ float g_dist[N_NODES];
__device__ float g_sel[SELN];
__device__ float g_top[TOPK];
__device__ int   g_selcnt;
__device__ int   g_thrbin;
__device__ int   g_cnt[NTOT];
__device__ int   g_rowptr[2 * (N_NODES + 1)];
__device__ int   g_cursor[NTOT];
__device__ int   g_esrc[2 * N_EDGES];

// ---------------- helpers ----------------
__device__ __forceinline__ uint32_t packbf(float lo_e, float hi_o) {
    uint32_t r;
    asm("cvt.rn.bf16x2.f32 %0, %1, %2;" : "=r"(r) : "f"(hi_o), "f"(lo_e));
    return r;
}
__device__ __forceinline__ void split2(float v0, float v1, uint32_t& h, uint32_t& l) {
    h = packbf(v0, v1);
    float h0 = __uint_as_float(h << 16);
    float h1 = __uint_as_float(h & 0xffff0000u);
    l = packbf(v0 - h0, v1 - h1);
}
__device__ __forceinline__ void mma_bf16(float* c, const uint32_t* a, const uint32_t* b) {
    asm volatile(
        "mma.sync.aligned.m16n8k16.row.col.f32.bf16.bf16.f32 "
        "{%0,%1,%2,%3}, {%4,%5,%6,%7}, {%8,%9}, {%0,%1,%2,%3};"
        : "+f"(c[0]), "+f"(c[1]), "+f"(c[2]), "+f"(c[3])
        : "r"(a[0]), "r"(a[1]), "r"(a[2]), "r"(a[3]), "r"(b[0]), "r"(b[1]));
}

// ---------------- CSR build (both graphs, batched) ----------------
__global__ void k_zero_cnt() {
    int i = blockIdx.x * blockDim.x + threadIdx.x;
    if (i < NTOT) g_cnt[i] = 0;
}
__global__ void k_hist2(const int* __restrict__ dst1, const int* __restrict__ dst2) {
    int e = blockIdx.x * blockDim.x + threadIdx.x;
    if (e >= 2 * N_EDGES) return;
    int gph = e >= N_EDGES;
    int le = e - gph * N_EDGES;
    int d = (gph ? dst2 : dst1)[le];
    atomicAdd(&g_cnt[gph * N_NODES + d], 1);
}
__global__ void k_scan2() {
    __shared__ int s[1024];
    __shared__ int carry;
    int t = threadIdx.x;
    int gph = blockIdx.x;                  // 0 or 1
    const int cbase = gph * N_NODES;
    const int rbase = gph * (N_NODES + 1);
    if (t == 0) carry = 0;
    __syncthreads();
    for (int base = 0; base < N_NODES; base += 1024) {
        int v = (base + t < N_NODES) ? g_cnt[cbase + base + t] : 0;
        s[t] = v;
        __syncthreads();
        for (int off = 1; off < 1024; off <<= 1) {
            int a = (t >= off) ? s[t - off] : 0;
            __syncthreads();
            s[t] += a;
            __syncthreads();
        }
        int exc = s[t] - v + carry;
        if (base + t < N_NODES) {
            g_rowptr[rbase + base + t] = exc;
            g_cursor[cbase + base + t] = exc;
        }
        __syncthreads();
        if (t == 0) carry = carry + s[1023];
        __syncthreads();
    }
    if (t == 0) g_rowptr[rbase + N_NODES] = carry;
}
__global__ void k_fill2(const int* __restrict__ src1, const int* __restrict__ dst1,
                        const int* __restrict__ src2, const int* __restrict__ dst2) {
    int e = blockIdx.x * blockDim.x + threadIdx.x;
    if (e >= 2 * N_EDGES) return;
    int gph = e >= N_EDGES;
    int le = e - gph * N_EDGES;
    int d = (gph ? dst2 : dst1)[le];
    int sv = (gph ? src2 : src1)[le];
    int pos = atomicAdd(&g_cursor[gph * N_NODES + d], 1);
    g_esrc[gph * N_EDGES + pos] = sv;
}

// ---------------- aggregation (both graphs): out[node] = x[node] + sum_j x[j] ----
template <int F>
__global__ void k_agg2(const float* __restrict__ xa, const float* __restrict__ xb,
                       float* __restrict__ out) {
    const int FV = F / 4;
    int node = blockIdx.x;                  // 0..39999
    int gph = node >= N_NODES;
    int local = node - gph * N_NODES;
    int t = threadIdx.x;
    __shared__ int ssrc[256];
    const float4* x4 = (const float4*)(gph ? xb : xa);
    float4 acc = x4[(size_t)local * FV + t];
    int beg = g_rowptr[gph * (N_NODES + 1) + local];
    int end = g_rowptr[gph * (N_NODES + 1) + local + 1];
    int eoff = gph * N_EDGES;
    for (int c = beg; c < end; c += 256) {
        int m = min(256, end - c);
        for (int i = t; i < m; i += FV) ssrc[i] = g_esrc[eoff + c + i];
        __syncthreads();
        for (int i = 0; i < m; i++) {
            float4 v = x4[(size_t)ssrc[i] * FV + t];
            acc.x += v.x; acc.y += v.y; acc.z += v.z; acc.w += v.w;
        }
        __syncthreads();
    }
    ((float4*)out)[(size_t)node * FV + t] = acc;
}

// ---------------- 3x-bf16 mma.sync GEMM: C[MPAD2,512] = relu(A @ W + b) ------
#define GSTRIDE 140
#define GMATW   (8 * GSTRIDE)

__global__ void __launch_bounds__(256)
k_gemm_mma(const float* __restrict__ A, const float* __restrict__ W,
           const float* __restrict__ bias, float* __restrict__ C, int K) {
    __shared__ uint32_t S[2][4][GMATW];
    int t = threadIdx.x, lane = t & 31, wid = t >> 5;
    int warp_m = wid >> 1, warp_n = wid & 1;
    int rowBase = blockIdx.y * 128;
    int colBase = blockIdx.x * 128;

    float acc[2][8][4];
#pragma unroll
    for (int i = 0; i < 2; i++)
#pragma unroll
        for (int j = 0; j < 8; j++)
#pragma unroll
            for (int q = 0; q < 4; q++) acc[i][j][q] = 0.f;

    int a_row = t >> 1;
    int a_half = t & 1;
    int b_k2 = t >> 5;
    int b_n0 = lane * 4;

    const float* Ap = A + (size_t)(rowBase + a_row) * K + a_half * 8;
    const float* Bp0 = W + (size_t)(2 * b_k2) * HDIM + colBase + b_n0;
    const float* Bp1 = Bp0 + HDIM;

    const int nk = K >> 4;
    float4 ra0, ra1, rb0, rb1;

    ra0 = *(const float4*)(Ap);
    ra1 = *(const float4*)(Ap + 4);
    rb0 = *(const float4*)(Bp0);
    rb1 = *(const float4*)(Bp1);

    for (int s = 0; s < nk; s++) {
        int buf = s & 1;
        uint32_t* Ah = S[buf][0];
        uint32_t* Al = S[buf][1];
        uint32_t* Bh = S[buf][2];
        uint32_t* Bl = S[buf][3];
        {
            float av[8] = {ra0.x, ra0.y, ra0.z, ra0.w, ra1.x, ra1.y, ra1.z, ra1.w};
#pragma unroll
            for (int i = 0; i < 4; i++) {
                uint32_t h, l;
                split2(av[2 * i], av[2 * i + 1], h, l);
                int idx = (a_half * 4 + i) * GSTRIDE + a_row;
                Ah[idx] = h; Al[idx] = l;
            }
            uint4 hh, ll;
            split2(rb0.x, rb1.x, hh.x, ll.x);
            split2(rb0.y, rb1.y, hh.y, ll.y);
            split2(rb0.z, rb1.z, hh.z, ll.z);
            split2(rb0.w, rb1.w, hh.w, ll.w);
            *(uint4*)&Bh[b_k2 * GSTRIDE + b_n0] = hh;
            *(uint4*)&Bl[b_k2 * GSTRIDE + b_n0] = ll;
        }
        __syncthreads();
        if (s + 1 < nk) {
            const float* Ap2 = Ap + (s + 1) * 16;
            const float* Bp2 = Bp0 + (size_t)(s + 1) * 16 * HDIM;
            ra0 = *(const float4*)(Ap2);
            ra1 = *(const float4*)(Ap2 + 4);
            rb0 = *(const float4*)(Bp2);
            rb1 = *(const float4*)(Bp2 + HDIM);
        }
        {
            int g = lane >> 2, q = lane & 3;
            uint32_t bhf[8][2], blf[8][2];
#pragma unroll
            for (int nt = 0; nt < 8; nt++) {
                int n = warp_n * 64 + nt * 8 + g;
                bhf[nt][0] = Bh[q * GSTRIDE + n];
                bhf[nt][1] = Bh[(q + 4) * GSTRIDE + n];
                blf[nt][0] = Bl[q * GSTRIDE + n];
                blf[nt][1] = Bl[(q + 4) * GSTRIDE + n];
            }
#pragma unroll
            for (int mt = 0; mt < 2; mt++) {
                int m = warp_m * 32 + mt * 16 + g;
                uint32_t ahf[4], alf[4];
                ahf[0] = Ah[q * GSTRIDE + m];
                ahf[1] = Ah[q * GSTRIDE + m + 8];
                ahf[2] = Ah[(q + 4) * GSTRIDE + m];
                ahf[3] = Ah[(q + 4) * GSTRIDE + m + 8];
                alf[0] = Al[q * GSTRIDE + m];
                alf[1] = Al[q * GSTRIDE + m + 8];
                alf[2] = Al[(q + 4) * GSTRIDE + m];
                alf[3] = Al[(q + 4) * GSTRIDE + m + 8];
#pragma unroll
                for (int nt = 0; nt < 8; nt++) {
                    mma_bf16(acc[mt][nt], ahf, bhf[nt]);
                    mma_bf16(acc[mt][nt], alf, bhf[nt]);
                    mma_bf16(acc[mt][nt], ahf, blf[nt]);
                }
            }
        }
        __syncthreads();
    }

    int g = lane >> 2;
    int cq = (lane & 3) * 2;
#pragma unroll
    for (int mt = 0; mt < 2; mt++) {
        int row = rowBase + warp_m * 32 + mt * 16 + g;
#pragma unroll
        for (int nt = 0; nt < 8; nt++) {
            int col = colBase + warp_n * 64 + nt * 8 + cq;
            float b0 = bias[col], b1 = bias[col + 1];
            float2 o0, o1;
            o0.x = fmaxf(acc[mt][nt][0] + b0, 0.f);
            o0.y = fmaxf(acc[mt][nt][1] + b1, 0.f);
            o1.x = fmaxf(acc[mt][nt][2] + b0, 0.f);
            o1.y = fmaxf(acc[mt][nt][3] + b1, 0.f);
            *(float2*)&C[(size_t)row * HDIM + col] = o0;
            *(float2*)&C[(size_t)(row + 8) * HDIM + col] = o1;
        }
    }
}

// ---------------- final linear [NTOT,512] @ [512,2] ----------------
__global__ void k_lin(const float* __restrict__ act, const float* __restrict__ w,
                      const float* __restrict__ b, float* __restrict__ o) {
    int warp = (blockIdx.x * blockDim.x + threadIdx.x) >> 5;
    int lane = threadIdx.x & 31;
    if (warp >= NTOT) return;
    float a0 = 0.f, a1 = 0.f;
    for (int k = lane; k < HDIM; k += 32) {
        float v = act[(size_t)warp * HDIM + k];
        a0 += v * w[k * 2];
        a1 += v * w[k * 2 + 1];
    }
#pragma unroll
    for (int off = 16; off; off >>= 1) {
        a0 += __shfl_down_sync(0xffffffffu, a0, off);
        a1 += __shfl_down_sync(0xffffffffu, a1, off);
    }
    if (lane == 0) {
        o[warp * 2]     = a0 + b[0];
        o[warp * 2 + 1] = a1 + b[1];
    }
}

// ---------------- pairwise distance ----------------
__global__ void k_dist() {
    int i = blockIdx.x * blockDim.x + threadIdx.x;
    if (i >= N_NODES) return;
    float dx = g_o[i * 2]     - g_o[(i + N_NODES) * 2]     + 1e-6f;
    float dy = g_o[i * 2 + 1] - g_o[(i + N_NODES) * 2 + 1] + 1e-6f;
    g_dist[i] = sqrtf(dx * dx + dy * dy);
}

// ---------------- top-k select: histogram threshold ----------------
__global__ void k_selhist() {
    __shared__ int hist[2048];
    int t = threadIdx.x;
    hist[t] = 0; hist[t + 1024] = 0;
    for (int i = t; i < SELN; i += 1024) g_sel[i] = -INFINITY;
    if (t == 0) g_selcnt = 0;
    __syncthreads();
    for (int i = t; i < N_NODES; i += 1024) {
        uint32_t bits = __float_as_uint(g_dist[i]);
        atomicAdd(&hist[bits >> 21], 1);
    }
    __syncthreads();
    if (t == 0) {
        int cum = 0, thr = 0;
        for (int b = 2047; b >= 0; b--) {
            cum += hist[b];
            if (cum >= TOPK) { thr = b; break; }
        }
        g_thrbin = thr;
    }
}
__global__ void k_compact() {
    int i = blockIdx.x * blockDim.x + threadIdx.x;
    if (i >= N_NODES) return;
    float d = g_dist[i];
    if ((int)(__float_as_uint(d) >> 21) >= g_thrbin) {
        int pos = atomicAdd(&g_selcnt, 1);
        if (pos < SELN) g_sel[pos] = d;
    }
}
__global__ void k_sortsel() {
    __shared__ float s[SELN];
    int t = threadIdx.x;
    for (int i = t; i < SELN; i += 1024) s[i] = g_sel[i];
    __syncthreads();
    for (int k = 2; k <= SELN; k <<= 1) {
        for (int j = k >> 1; j > 0; j >>= 1) {
            for (int i = t; i < SELN; i += 1024) {
                int ixj = i ^ j;
                if (ixj > i) {
                    bool dsc = (i & k) == 0;
                    float a = s[i], c = s[ixj];
                    bool sw = dsc ? (a < c) : (a > c);
                    if (sw) { s[i] = c; s[ixj] = a; }
                }
            }
            __syncthreads();
        }
    }
    for (int i = t; i < TOPK; i += 1024) g_top[i] = s[i];
}

// ---------------- head MLP ----------------
__global__ void k_mlp(const float* __restrict__ fc1w, const float* __restrict__ fc1b,
                      const float* __restrict__ ln1g, const float* __restrict__ ln1b,
                      const float* __restrict__ fc2w, const float* __restrict__ fc2b,
                      const float* __restrict__ ln2g, const float* __restrict__ ln2b,
                      const float* __restrict__ fc3w, const float* __restrict__ fc3b,
                      float* __restrict__ out) {
    __shared__ float vals[TOPK];
    __shared__ float h1[128];
    __shared__ float part[4][128];
    __shared__ float h2[512];
    __shared__ float red[512];
    int t = threadIdx.x;
    for (int i = t; i < TOPK; i += 512) vals[i] = g_top[i];
    __syncthreads();
    {
        int j = t & 127, c = t >> 7;
        float acc = 0.f;
        for (int i = c * 250; i < (c + 1) * 250; i++) acc += vals[i] * fc1w[i * 128 + j];
        part[c][j] = acc;
    }
    __syncthreads();
    if (t < 128) h1[t] = part[0][t] + part[1][t] + part[2][t] + part[3][t] + fc1b[t];
    __syncthreads();
    red[t] = (t < 128) ? h1[t] : 0.f;
    __syncthreads();
    for (int off = 256; off; off >>= 1) { if (t < off) red[t] += red[t + off]; __syncthreads(); }
    float mean1 = red[0] / 128.f;
    __syncthreads();
    red[t] = (t < 128) ? (h1[t] - mean1) * (h1[t] - mean1) : 0.f;
    __syncthreads();
    for (int off = 256; off; off >>= 1) { if (t < off) red[t] += red[t + off]; __syncthreads(); }
    float var1 = red[0] / 128.f;
    __syncthreads();
    if (t < 128) {
        float v = (h1[t] - mean1) * rsqrtf(var1 + 1e-5f) * ln1g[t] + ln1b[t];
        h1[t] = fmaxf(v, 0.f);
    }
    __syncthreads();
    {
        float acc = fc2b[t];
        for (int i = 0; i < 128; i++) acc += h1[i] * fc2w[i * 512 + t];
        h2[t] = acc;
    }
    __syncthreads();
    red[t] = h2[t];
    __syncthreads();
    for (int off = 256; off; off >>= 1) { if (t < off) red[t] += red[t + off]; __syncthreads(); }
    float mean2 = red[0] / 512.f;
    __syncthreads();
    red[t] = (h2[t] - mean2) * (h2[t] - mean2);
    __syncthreads();
    for (int off = 256; off; off >>= 1) { if (t < off) red[t] += red[t + off]; __syncthreads(); }
    float var2 = red[0] / 512.f;
    __syncthreads();
    float hr = fmaxf((h2[t] - mean2) * rsqrtf(var2 + 1e-5f) * ln2g[t] + ln2b[t], 0.f);
    red[t] = hr * fc3w[t];
    __syncthreads();
    for (int off = 256; off; off >>= 1) { if (t < off) red[t] += red[t + off]; __syncthreads(); }
    if (t == 0) out[0] = 1.f / (1.f + expf(-(red[0] + fc3b[0])));
}

// ---------------- launch ----------------
extern "C" void kernel_launch(void* const* d_in, const int* in_sizes, int n_in,
                              void* d_out, int out_size) {
    const float* x1   = (const float*)d_in[0];
    const int*   ei1  = (const int*)d_in[1];
    const float* x2   = (const float*)d_in[2];
    const int*   ei2  = (const int*)d_in[3];
    const float* w11  = (const float*)d_in[4];
    const float* b11  = (const float*)d_in[5];
    const float* w12  = (const float*)d_in[6];
    const float* b12  = (const float*)d_in[7];
    const float* w21  = (const float*)d_in[8];
    const float* b21  = (const float*)d_in[9];
    const float* w22  = (const float*)d_in[10];
    const float* b22  = (const float*)d_in[11];
    const float* w31  = (const float*)d_in[12];
    const float* b31  = (const float*)d_in[13];
    const float* w32  = (const float*)d_in[14];
    const float* b32  = (const float*)d_in[15];
    const float* linw = (const float*)d_in[16];
    const float* linb = (const float*)d_in[17];
    const float* fc1w = (const float*)d_in[18];
    const float* fc1b = (const float*)d_in[19];
    const float* ln1g = (const float*)d_in[20];
    const float* ln1b = (const float*)d_in[21];
    const float* fc2w = (const float*)d_in[22];
    const float* fc2b = (const float*)d_in[23];
    const float* ln2g = (const float*)d_in[24];
    const float* ln2b = (const float*)d_in[25];
    const float* fc3w = (const float*)d_in[26];
    const float* fc3b = (const float*)d_in[27];
    float* out = (float*)d_out;

    const int* src1 = ei1;
    const int* dst1 = ei1 + N_EDGES;
    const int* src2 = ei2;
    const int* dst2 = ei2 + N_EDGES;

    float *p_agg, *p_tmp, *p_act, *p_o;
    cudaGetSymbolAddress((void**)&p_agg, g_agg);
    cudaGetSymbolAddress((void**)&p_tmp, g_tmp);
    cudaGetSymbolAddress((void**)&p_act, g_act);
    cudaGetSymbolAddress((void**)&p_o, g_o);

    dim3 ggrid(HDIM / 128, MT2);
    const int E2B = (2 * N_EDGES + 255) / 256;
    const int N2B = (NTOT + 255) / 256;
    const int NB = (N_NODES + 255) / 256;

    // batched CSR for both graphs
    k_zero_cnt<<<N2B, 256>>>();
    k_hist2<<<E2B, 256>>>(dst1, dst2);
    k_scan2<<<2, 1024>>>();
    k_fill2<<<E2B, 256>>>(src1, dst1, src2, dst2);

    // layer 1 (FIN=256 -> H)
    k_agg2<FIN_DIM><<<NTOT, FIN_DIM / 4>>>(x1, x2, p_agg);
    k_gemm_mma<<<ggrid, 256>>>(p_agg, w11, b11, p_tmp, FIN_DIM);
    k_gemm_mma<<<ggrid, 256>>>(p_tmp, w12, b12, p_act, HDIM);
    // layer 2
    k_agg2<HDIM><<<NTOT, HDIM / 4>>>(p_act, p_act + (size_t)N_NODES * HDIM, p_agg);
    k_gemm_mma<<<ggrid, 256>>>(p_agg, w21, b21, p_tmp, HDIM);
    k_gemm_mma<<<ggrid, 256>>>(p_tmp, w22, b22, p_act, HDIM);
    // layer 3
    k_agg2<HDIM><<<NTOT, HDIM / 4>>>(p_act, p_act + (size_t)N_NODES * HDIM, p_agg);
    k_gemm_mma<<<ggrid, 256>>>(p_agg, w31, b31, p_tmp, HDIM);
    k_gemm_mma<<<ggrid, 256>>>(p_tmp, w32, b32, p_act, HDIM);
    // lin head -> [NTOT,2]
    k_lin<<<(NTOT * 32 + 255) / 256, 256>>>(p_act, linw, linb, p_o);

    k_dist<<<NB, 256>>>();
    k_selhist<<<1, 1024>>>();
    k_compact<<<NB, 256>>>();
    k_sortsel<<<1, 1024>>>();
    k_mlp<<<1, 512>>>(fc1w, fc1b, ln1g, ln1b, fc2w, fc2b, ln2g, ln2b, fc3w, fc3b, out);
}